// round 3
// baseline (speedup 1.0000x reference)
#include <cuda_runtime.h>
#include <math.h>

#define BB 4
#define SS 2048
#define EE 1024
#define HH 16
#define DD 64
#define NROWS (BB * SS)      // 8192
#define K3E   (3 * EE)       // 3072

// Scratch (static device allocations are allowed; cudaMalloc is not)
__device__ float g_qkv[(size_t)NROWS * K3E];   // 96 MB: [8192, 3072]
__device__ float g_ctx[(size_t)NROWS * EE];    // 32 MB: [B,H,S,D] contiguous == [8192,1024]

// ---------------------------------------------------------------------------
// SGEMM + bias: C[M,N] = A[M,K] @ B[K,N] + bias[N]  (all row-major fp32)
// 128x128 block tile, BK=8, 8x8 per thread, 256 threads.
// M%128==0, N%128==0, K%8==0 guaranteed by problem sizes.
// ---------------------------------------------------------------------------
__global__ __launch_bounds__(256, 2) void sgemm_bias_kernel(
    const float* __restrict__ A, const float* __restrict__ B,
    const float* __restrict__ bias, float* __restrict__ C,
    int M, int N, int K)
{
    __shared__ float As[8][128];
    __shared__ float Bs[8][132];   // pad 132 (row = 528B, 16B-aligned)

    const int tid = threadIdx.x;
    const int tx  = tid & 15;      // 0..15 -> col group
    const int ty  = tid >> 4;      // 0..15 -> row group
    const int row0 = blockIdx.y * 128;
    const int col0 = blockIdx.x * 128;

    // A load: 128 rows x 8 cols, one float4 per thread
    const int a_row = tid >> 1;          // 0..127
    const int a_col = (tid & 1) << 2;    // 0 or 4
    // B load: 8 rows x 128 cols, one float4 per thread
    const int b_row = tid >> 5;          // 0..7
    const int b_col = (tid & 31) << 2;   // 0..124

    const float* Aptr = A + (size_t)(row0 + a_row) * K + a_col;
    const float* Bptr = B + (size_t)b_row * N + col0 + b_col;

    float acc[8][8];
#pragma unroll
    for (int i = 0; i < 8; i++)
#pragma unroll
        for (int j = 0; j < 8; j++) acc[i][j] = 0.0f;

    for (int k0 = 0; k0 < K; k0 += 8) {
        float4 av = *(const float4*)(Aptr + k0);
        float4 bv = *(const float4*)(Bptr + (size_t)k0 * N);
        As[a_col + 0][a_row] = av.x;
        As[a_col + 1][a_row] = av.y;
        As[a_col + 2][a_row] = av.z;
        As[a_col + 3][a_row] = av.w;
        *(float4*)&Bs[b_row][b_col] = bv;
        __syncthreads();

#pragma unroll
        for (int k = 0; k < 8; k++) {
            float a0[8], b0[8];
            *(float4*)&a0[0] = *(const float4*)&As[k][ty * 8];
            *(float4*)&a0[4] = *(const float4*)&As[k][ty * 8 + 4];
            *(float4*)&b0[0] = *(const float4*)&Bs[k][tx * 8];
            *(float4*)&b0[4] = *(const float4*)&Bs[k][tx * 8 + 4];
#pragma unroll
            for (int i = 0; i < 8; i++)
#pragma unroll
                for (int j = 0; j < 8; j++)
                    acc[i][j] += a0[i] * b0[j];
        }
        __syncthreads();
    }

#pragma unroll
    for (int i = 0; i < 8; i++) {
        const int r = row0 + ty * 8 + i;
#pragma unroll
        for (int j = 0; j < 8; j += 4) {
            const int c = col0 + tx * 8 + j;
            float4 o;
            o.x = acc[i][j + 0] + bias[c + 0];
            o.y = acc[i][j + 1] + bias[c + 1];
            o.z = acc[i][j + 2] + bias[c + 2];
            o.w = acc[i][j + 3] + bias[c + 3];
            *(float4*)&C[(size_t)r * N + c] = o;
        }
    }
}

// ---------------------------------------------------------------------------
// Causal FlashAttention (fp32).
// Grid: (S/64 q-tiles, B*H). Block: 256 threads (16x16, 4x4 per thread).
// Q/K/V read strided from g_qkv: row b*S+s, cols h*192 + {0,64,128}.
// Output written to g_ctx in [B,H,S,D] contiguous order (matches the
// reference's transpose-free reshape).
// Dynamic smem: Qs/Ks/Vs/Ps each [64][68] floats = 69632 B total.
// ---------------------------------------------------------------------------
#define FLASH_SMEM_BYTES (4 * 64 * 68 * 4)

__global__ __launch_bounds__(256, 1) void flash_attn_kernel(
    const float* __restrict__ qkv, float* __restrict__ ctx)
{
    extern __shared__ float sm[];
    float (*Qs)[68] = (float(*)[68])(sm);               // [d][row]
    float (*Ks)[68] = (float(*)[68])(sm + 64 * 68);     // [d][col]
    float (*Vs)[68] = (float(*)[68])(sm + 2 * 64 * 68); // [key][d]
    float (*Ps)[68] = (float(*)[68])(sm + 3 * 64 * 68); // [key][row]

    const int bh = blockIdx.y;             // b*H + h
    const int b  = bh >> 4;
    const int h  = bh & 15;
    const int qt = blockIdx.x;
    const int q0 = qt * 64;
    const float scale = 0.125f;            // 1/sqrt(64)

    const int tid = threadIdx.x;
    const int tx  = tid & 15;              // dim/key-col group
    const int ty  = tid >> 4;              // row group

    const float* qbase = qkv + (size_t)b * SS * K3E + h * (3 * DD);

    // Load Q tile transposed: Qs[d][row]
#pragma unroll
    for (int it = 0; it < 4; it++) {
        int idx = it * 256 + tid;
        int row = idx >> 4;                // 0..63
        int d4  = (idx & 15) << 2;         // 0..60
        float4 v = *(const float4*)(qbase + (size_t)(q0 + row) * K3E + d4);
        Qs[d4 + 0][row] = v.x;
        Qs[d4 + 1][row] = v.y;
        Qs[d4 + 2][row] = v.z;
        Qs[d4 + 3][row] = v.w;
    }

    float m_i[4], l_i[4], o[4][4];
#pragma unroll
    for (int i = 0; i < 4; i++) {
        m_i[i] = -1e30f;
        l_i[i] = 0.0f;
#pragma unroll
        for (int j = 0; j < 4; j++) o[i][j] = 0.0f;
    }

    for (int kt = 0; kt <= qt; kt++) {
        const int k0 = kt * 64;
        __syncthreads();   // previous PV done before overwriting Ks/Vs

        // Load K transposed, V natural
#pragma unroll
        for (int it = 0; it < 4; it++) {
            int idx = it * 256 + tid;
            int row = idx >> 4;
            int d4  = (idx & 15) << 2;
            const float* kb = qbase + DD + (size_t)(k0 + row) * K3E + d4;
            float4 kv = *(const float4*)kb;
            Ks[d4 + 0][row] = kv.x;
            Ks[d4 + 1][row] = kv.y;
            Ks[d4 + 2][row] = kv.z;
            Ks[d4 + 3][row] = kv.w;
            const float* vb = qbase + 2 * DD + (size_t)(k0 + row) * K3E + d4;
            *(float4*)&Vs[row][d4] = *(const float4*)vb;
        }
        __syncthreads();

        // S = Q @ K^T
        float s[4][4];
#pragma unroll
        for (int i = 0; i < 4; i++)
#pragma unroll
            for (int j = 0; j < 4; j++) s[i][j] = 0.0f;

#pragma unroll
        for (int d = 0; d < 64; d++) {
            float a[4], bb[4];
            *(float4*)a  = *(const float4*)&Qs[d][ty * 4];
            *(float4*)bb = *(const float4*)&Ks[d][tx * 4];
#pragma unroll
            for (int i = 0; i < 4; i++)
#pragma unroll
                for (int j = 0; j < 4; j++)
                    s[i][j] += a[i] * bb[j];
        }

#pragma unroll
        for (int i = 0; i < 4; i++)
#pragma unroll
            for (int j = 0; j < 4; j++) s[i][j] *= scale;

        if (kt == qt) {
            // causal mask inside diagonal tile
#pragma unroll
            for (int i = 0; i < 4; i++) {
                const int qi = q0 + ty * 4 + i;
#pragma unroll
                for (int j = 0; j < 4; j++) {
                    const int kj = k0 + tx * 4 + j;
                    if (kj > qi) s[i][j] = -1e30f;
                }
            }
        }

        // Online softmax update (row reductions over 16-lane segments)
#pragma unroll
        for (int i = 0; i < 4; i++) {
            float mt = fmaxf(fmaxf(s[i][0], s[i][1]), fmaxf(s[i][2], s[i][3]));
#pragma unroll
            for (int off = 8; off > 0; off >>= 1)
                mt = fmaxf(mt, __shfl_xor_sync(0xffffffffu, mt, off, 16));
            const float m_new = fmaxf(m_i[i], mt);
            const float alpha = __expf(m_i[i] - m_new);
            float rs = 0.0f;
#pragma unroll
            for (int j = 0; j < 4; j++) {
                const float p = __expf(s[i][j] - m_new);
                s[i][j] = p;
                rs += p;
            }
#pragma unroll
            for (int off = 8; off > 0; off >>= 1)
                rs += __shfl_xor_sync(0xffffffffu, rs, off, 16);
            l_i[i] = l_i[i] * alpha + rs;
            m_i[i] = m_new;
#pragma unroll
            for (int j = 0; j < 4; j++) o[i][j] *= alpha;
        }

        // Store P transposed: Ps[key][row]
#pragma unroll
        for (int i = 0; i < 4; i++)
#pragma unroll
            for (int j = 0; j < 4; j++)
                Ps[tx * 4 + j][ty * 4 + i] = s[i][j];
        __syncthreads();

        // O += P @ V
#pragma unroll
        for (int k = 0; k < 64; k++) {
            float a[4], bb[4];
            *(float4*)a  = *(const float4*)&Ps[k][ty * 4];
            *(float4*)bb = *(const float4*)&Vs[k][tx * 4];
#pragma unroll
            for (int i = 0; i < 4; i++)
#pragma unroll
                for (int j = 0; j < 4; j++)
                    o[i][j] += a[i] * bb[j];
        }
    }

    // Finalize and store O -> ctx [B,H,S,D] contiguous
    float* cbase = ctx + ((size_t)bh * SS + q0) * DD;
#pragma unroll
    for (int i = 0; i < 4; i++) {
        const float inv = 1.0f / l_i[i];
        float4 ov;
        ov.x = o[i][0] * inv;
        ov.y = o[i][1] * inv;
        ov.z = o[i][2] * inv;
        ov.w = o[i][3] * inv;
        *(float4*)&cbase[(size_t)(ty * 4 + i) * DD + tx * 4] = ov;
    }
}

// ---------------------------------------------------------------------------
// Launch
// ---------------------------------------------------------------------------
extern "C" void kernel_launch(void* const* d_in, const int* in_sizes, int n_in,
                              void* d_out, int out_size)
{
    const float* x    = (const float*)d_in[0];
    // d_in[1] = causal mask (known tril -> handled analytically)
    const float* Wqkv = (const float*)d_in[2];
    const float* bqkv = (const float*)d_in[3];
    const float* Wo   = (const float*)d_in[4];
    const float* bo   = (const float*)d_in[5];
    float* out = (float*)d_out;

    float* qkv = nullptr;
    float* ctx = nullptr;
    cudaGetSymbolAddress((void**)&qkv, g_qkv);
    cudaGetSymbolAddress((void**)&ctx, g_ctx);

    cudaFuncSetAttribute(flash_attn_kernel,
                         cudaFuncAttributeMaxDynamicSharedMemorySize,
                         FLASH_SMEM_BYTES);

    // 1) QKV projection: [8192,1024] @ [1024,3072] + bqkv
    {
        dim3 grid(K3E / 128, NROWS / 128);   // (24, 64)
        sgemm_bias_kernel<<<grid, 256>>>(x, Wqkv, bqkv, qkv, NROWS, K3E, EE);
    }
    // 2) Causal flash attention per (b,h)
    {
        dim3 grid(SS / 64, BB * HH);         // (32, 64)
        flash_attn_kernel<<<grid, 256, FLASH_SMEM_BYTES>>>(qkv, ctx);
    }
    // 3) Output projection: ctx flat [8192,1024] @ [1024,1024] + bo
    {
        dim3 grid(EE / 128, NROWS / 128);    // (8, 64)
        sgemm_bias_kernel<<<grid, 256>>>(ctx, Wo, bo, out, NROWS, EE, EE);
    }
}

// round 7
// speedup vs baseline: 1.5365x; 1.5365x over previous
#include <cuda_runtime.h>
#include <math.h>

#define BB 4
#define SS 2048
#define EE 1024
#define HH 16
#define DD 64
#define NROWS (BB * SS)      // 8192
#define K3E   (3 * EE)       // 3072

// Scratch (static device allocations are allowed; cudaMalloc is not)
__device__ float g_qkv[(size_t)NROWS * K3E];   // 96 MB: [8192, 3072]
__device__ float g_ctx[(size_t)NROWS * EE];    // 32 MB: [B,H,S,D] contiguous == [8192,1024]

// ---------------------------------------------------------------------------
// SGEMM + bias: C[M,N] = A[M,K] @ B[K,N] + bias[N]  (all row-major fp32)
// 128x128 block tile, BK=8, 8x8 per thread, 256 threads.
// M%128==0, N%128==0, K%8==0 guaranteed by problem sizes.
// ---------------------------------------------------------------------------
__global__ __launch_bounds__(256, 2) void sgemm_bias_kernel(
    const float* __restrict__ A, const float* __restrict__ B,
    const float* __restrict__ bias, float* __restrict__ C,
    int M, int N, int K)
{
    __shared__ float As[8][128];
    __shared__ float Bs[8][132];   // pad 132 (row = 528B, 16B-aligned)

    const int tid = threadIdx.x;
    const int tx  = tid & 15;      // 0..15 -> col group
    const int ty  = tid >> 4;      // 0..15 -> row group
    const int row0 = blockIdx.y * 128;
    const int col0 = blockIdx.x * 128;

    // A load: 128 rows x 8 cols, one float4 per thread
    const int a_row = tid >> 1;          // 0..127
    const int a_col = (tid & 1) << 2;    // 0 or 4
    // B load: 8 rows x 128 cols, one float4 per thread
    const int b_row = tid >> 5;          // 0..7
    const int b_col = (tid & 31) << 2;   // 0..124

    const float* Aptr = A + (size_t)(row0 + a_row) * K + a_col;
    const float* Bptr = B + (size_t)b_row * N + col0 + b_col;

    float acc[8][8];
#pragma unroll
    for (int i = 0; i < 8; i++)
#pragma unroll
        for (int j = 0; j < 8; j++) acc[i][j] = 0.0f;

    for (int k0 = 0; k0 < K; k0 += 8) {
        float4 av = *(const float4*)(Aptr + k0);
        float4 bv = *(const float4*)(Bptr + (size_t)k0 * N);
        As[a_col + 0][a_row] = av.x;
        As[a_col + 1][a_row] = av.y;
        As[a_col + 2][a_row] = av.z;
        As[a_col + 3][a_row] = av.w;
        *(float4*)&Bs[b_row][b_col] = bv;
        __syncthreads();

#pragma unroll
        for (int k = 0; k < 8; k++) {
            float a0[8], b0[8];
            *(float4*)&a0[0] = *(const float4*)&As[k][ty * 8];
            *(float4*)&a0[4] = *(const float4*)&As[k][ty * 8 + 4];
            *(float4*)&b0[0] = *(const float4*)&Bs[k][tx * 8];
            *(float4*)&b0[4] = *(const float4*)&Bs[k][tx * 8 + 4];
#pragma unroll
            for (int i = 0; i < 8; i++)
#pragma unroll
                for (int j = 0; j < 8; j++)
                    acc[i][j] += a0[i] * b0[j];
        }
        __syncthreads();
    }

#pragma unroll
    for (int i = 0; i < 8; i++) {
        const int r = row0 + ty * 8 + i;
#pragma unroll
        for (int j = 0; j < 8; j += 4) {
            const int c = col0 + tx * 8 + j;
            float4 o;
            o.x = acc[i][j + 0] + bias[c + 0];
            o.y = acc[i][j + 1] + bias[c + 1];
            o.z = acc[i][j + 2] + bias[c + 2];
            o.w = acc[i][j + 3] + bias[c + 3];
            *(float4*)&C[(size_t)r * N + c] = o;
        }
    }
}

// ---------------------------------------------------------------------------
// Causal FlashAttention (fp32).
// Grid: (S/64 q-tiles, B*H). Block: 256 threads (16x16, 4x4 per thread).
// Q/K/V read strided from g_qkv: row b*S+s, cols h*192 + {0,64,128}.
// Output written to g_ctx in [B,H,S,D] contiguous order (matches the
// reference's transpose-free reshape).
// Dynamic smem: Qs/Ks/Vs/Ps each [64][68] floats = 69632 B total.
// ---------------------------------------------------------------------------
#define FLASH_SMEM_BYTES (4 * 64 * 68 * 4)

__global__ __launch_bounds__(256, 1) void flash_attn_kernel(
    const float* __restrict__ qkv, float* __restrict__ ctx)
{
    extern __shared__ float sm[];
    float (*Qs)[68] = (float(*)[68])(sm);               // [d][row]
    float (*Ks)[68] = (float(*)[68])(sm + 64 * 68);     // [d][col]
    float (*Vs)[68] = (float(*)[68])(sm + 2 * 64 * 68); // [key][d]
    float (*Ps)[68] = (float(*)[68])(sm + 3 * 64 * 68); // [key][row]

    const int bh = blockIdx.y;             // b*H + h
    const int b  = bh >> 4;
    const int h  = bh & 15;
    const int qt = blockIdx.x;
    const int q0 = qt * 64;
    const float scale = 0.125f;            // 1/sqrt(64)

    const int tid = threadIdx.x;
    const int tx  = tid & 15;              // dim/key-col group
    const int ty  = tid >> 4;              // row group

    const float* qbase = qkv + (size_t)b * SS * K3E + h * (3 * DD);

    // Load Q tile transposed: Qs[d][row]
#pragma unroll
    for (int it = 0; it < 4; it++) {
        int idx = it * 256 + tid;
        int row = idx >> 4;                // 0..63
        int d4  = (idx & 15) << 2;         // 0..60
        float4 v = *(const float4*)(qbase + (size_t)(q0 + row) * K3E + d4);
        Qs[d4 + 0][row] = v.x;
        Qs[d4 + 1][row] = v.y;
        Qs[d4 + 2][row] = v.z;
        Qs[d4 + 3][row] = v.w;
    }

    float m_i[4], l_i[4], o[4][4];
#pragma unroll
    for (int i = 0; i < 4; i++) {
        m_i[i] = -1e30f;
        l_i[i] = 0.0f;
#pragma unroll
        for (int j = 0; j < 4; j++) o[i][j] = 0.0f;
    }

    for (int kt = 0; kt <= qt; kt++) {
        const int k0 = kt * 64;
        __syncthreads();   // previous PV done before overwriting Ks/Vs

        // Load K transposed, V natural
#pragma unroll
        for (int it = 0; it < 4; it++) {
            int idx = it * 256 + tid;
            int row = idx >> 4;
            int d4  = (idx & 15) << 2;
            const float* kb = qbase + DD + (size_t)(k0 + row) * K3E + d4;
            float4 kv = *(const float4*)kb;
            Ks[d4 + 0][row] = kv.x;
            Ks[d4 + 1][row] = kv.y;
            Ks[d4 + 2][row] = kv.z;
            Ks[d4 + 3][row] = kv.w;
            const float* vb = qbase + 2 * DD + (size_t)(k0 + row) * K3E + d4;
            *(float4*)&Vs[row][d4] = *(const float4*)vb;
        }
        __syncthreads();

        // S = Q @ K^T
        float s[4][4];
#pragma unroll
        for (int i = 0; i < 4; i++)
#pragma unroll
            for (int j = 0; j < 4; j++) s[i][j] = 0.0f;

#pragma unroll
        for (int d = 0; d < 64; d++) {
            float a[4], bb[4];
            *(float4*)a  = *(const float4*)&Qs[d][ty * 4];
            *(float4*)bb = *(const float4*)&Ks[d][tx * 4];
#pragma unroll
            for (int i = 0; i < 4; i++)
#pragma unroll
                for (int j = 0; j < 4; j++)
                    s[i][j] += a[i] * bb[j];
        }

#pragma unroll
        for (int i = 0; i < 4; i++)
#pragma unroll
            for (int j = 0; j < 4; j++) s[i][j] *= scale;

        if (kt == qt) {
            // causal mask inside diagonal tile
#pragma unroll
            for (int i = 0; i < 4; i++) {
                const int qi = q0 + ty * 4 + i;
#pragma unroll
                for (int j = 0; j < 4; j++) {
                    const int kj = k0 + tx * 4 + j;
                    if (kj > qi) s[i][j] = -1e30f;
                }
            }
        }

        // Online softmax update (row reductions over 16-lane segments)
#pragma unroll
        for (int i = 0; i < 4; i++) {
            float mt = fmaxf(fmaxf(s[i][0], s[i][1]), fmaxf(s[i][2], s[i][3]));
#pragma unroll
            for (int off = 8; off > 0; off >>= 1)
                mt = fmaxf(mt, __shfl_xor_sync(0xffffffffu, mt, off, 16));
            const float m_new = fmaxf(m_i[i], mt);
            const float alpha = __expf(m_i[i] - m_new);
            float rs = 0.0f;
#pragma unroll
            for (int j = 0; j < 4; j++) {
                const float p = __expf(s[i][j] - m_new);
                s[i][j] = p;
                rs += p;
            }
#pragma unroll
            for (int off = 8; off > 0; off >>= 1)
                rs += __shfl_xor_sync(0xffffffffu, rs, off, 16);
            l_i[i] = l_i[i] * alpha + rs;
            m_i[i] = m_new;
#pragma unroll
            for (int j = 0; j < 4; j++) o[i][j] *= alpha;
        }

        // Store P transposed: Ps[key][row]
#pragma unroll
        for (int i = 0; i < 4; i++)
#pragma unroll
            for (int j = 0; j < 4; j++)
                Ps[tx * 4 + j][ty * 4 + i] = s[i][j];
        __syncthreads();

        // O += P @ V
#pragma unroll
        for (int k = 0; k < 64; k++) {
            float a[4], bb[4];
            *(float4*)a  = *(const float4*)&Ps[k][ty * 4];
            *(float4*)bb = *(const float4*)&Vs[k][tx * 4];
#pragma unroll
            for (int i = 0; i < 4; i++)
#pragma unroll
                for (int j = 0; j < 4; j++)
                    o[i][j] += a[i] * bb[j];
        }
    }

    // Finalize and store O -> ctx [B,H,S,D] contiguous
    float* cbase = ctx + ((size_t)bh * SS + q0) * DD;
#pragma unroll
    for (int i = 0; i < 4; i++) {
        const float inv = 1.0f / l_i[i];
        float4 ov;
        ov.x = o[i][0] * inv;
        ov.y = o[i][1] * inv;
        ov.z = o[i][2] * inv;
        ov.w = o[i][3] * inv;
        *(float4*)&cbase[(size_t)(ty * 4 + i) * DD + tx * 4] = ov;
    }
}

// ---------------------------------------------------------------------------
// Launch
// ---------------------------------------------------------------------------
extern "C" void kernel_launch(void* const* d_in, const int* in_sizes, int n_in,
                              void* d_out, int out_size)
{
    const float* x    = (const float*)d_in[0];
    // d_in[1] = causal mask (known tril -> handled analytically)
    const float* Wqkv = (const float*)d_in[2];
    const float* bqkv = (const float*)d_in[3];
    const float* Wo   = (const float*)d_in[4];
    const float* bo   = (const float*)d_in[5];
    float* out = (float*)d_out;

    float* qkv = nullptr;
    float* ctx = nullptr;
    cudaGetSymbolAddress((void**)&qkv, g_qkv);
    cudaGetSymbolAddress((void**)&ctx, g_ctx);

    cudaFuncSetAttribute(flash_attn_kernel,
                         cudaFuncAttributeMaxDynamicSharedMemorySize,
                         FLASH_SMEM_BYTES);

    // 1) QKV projection: [8192,1024] @ [1024,3072] + bqkv
    {
        dim3 grid(K3E / 128, NROWS / 128);   // (24, 64)
        sgemm_bias_kernel<<<grid, 256>>>(x, Wqkv, bqkv, qkv, NROWS, K3E, EE);
    }
    // 2) Causal flash attention per (b,h)
    {
        dim3 grid(SS / 64, BB * HH);         // (32, 64)
        flash_attn_kernel<<<grid, 256, FLASH_SMEM_BYTES>>>(qkv, ctx);
    }
    // 3) Output projection: ctx flat [8192,1024] @ [1024,1024] + bo
    {
        dim3 grid(EE / 128, NROWS / 128);    // (8, 64)
        sgemm_bias_kernel<<<grid, 256>>>(ctx, Wo, bo, out, NROWS, EE, EE);
    }
}

// round 8
// speedup vs baseline: 2.7736x; 1.8051x over previous
#include <cuda_runtime.h>
#include <cuda_bf16.h>
#include <math.h>

typedef unsigned int u32;

#define BB 4
#define SS 2048
#define EE 1024
#define HH 16
#define DD 64
#define NROWS 8192
#define K3E 3072
#define NW3 1536   // words per qkv row (K3E/2)
#define EW  512    // words per E row

// ---------------------------------------------------------------------------
// Scratch: hi/lo split bf16 word buffers (static device allocs are allowed)
// ---------------------------------------------------------------------------
__device__ u32 g_xh[(size_t)NROWS * EW];
__device__ u32 g_xl[(size_t)NROWS * EW];
__device__ u32 g_wqh[(size_t)EE * NW3];
__device__ u32 g_wql[(size_t)EE * NW3];
__device__ u32 g_woh[(size_t)EE * EW];
__device__ u32 g_wol[(size_t)EE * EW];
__device__ u32 g_qkvh[(size_t)NROWS * NW3];
__device__ u32 g_qkvl[(size_t)NROWS * NW3];
__device__ u32 g_ctxh[(size_t)NROWS * EW];
__device__ u32 g_ctxl[(size_t)NROWS * EW];

// ---------------------------------------------------------------------------
// Helpers
// ---------------------------------------------------------------------------
__device__ __forceinline__ void split2(float x, float y, u32& h, u32& l) {
    __nv_bfloat162 hb = __floats2bfloat162_rn(x, y);   // .x = x (low 16 bits)
    h = *reinterpret_cast<u32*>(&hb);
    float rx = x - __bfloat162float(hb.x);
    float ry = y - __bfloat162float(hb.y);
    __nv_bfloat162 lb = __floats2bfloat162_rn(rx, ry);
    l = *reinterpret_cast<u32*>(&lb);
}

// D(16x8 f32) += A(16x16 bf16 row) * B(16x8 bf16 col)
__device__ __forceinline__ void mma_bf16(float* c, const u32* a, u32 b0, u32 b1) {
    asm volatile(
        "mma.sync.aligned.m16n8k16.row.col.f32.bf16.bf16.f32 "
        "{%0,%1,%2,%3}, {%4,%5,%6,%7}, {%8,%9}, {%0,%1,%2,%3};"
        : "+f"(c[0]), "+f"(c[1]), "+f"(c[2]), "+f"(c[3])
        : "r"(a[0]), "r"(a[1]), "r"(a[2]), "r"(a[3]), "r"(b0), "r"(b1));
}

// ---------------------------------------------------------------------------
// Split fp32 array -> hi/lo bf16 word arrays
// ---------------------------------------------------------------------------
__global__ void split_kernel(const float* __restrict__ in,
                             u32* __restrict__ h, u32* __restrict__ l,
                             int nwords) {
    int i = blockIdx.x * 256 + threadIdx.x;
    if (i < nwords) {
        float2 v = ((const float2*)in)[i];
        u32 hw, lw;
        split2(v.x, v.y, hw, lw);
        h[i] = hw;
        l[i] = lw;
    }
}

// ---------------------------------------------------------------------------
// GEMM bf16x3: C[M,N] = (Ah+Al)[M,K] @ (Bh+Bl)[K,N] + bias
// 128x128x32 tile, 256 threads (8 warps, warp tile 32x64).
// A smem: [128 rows][20 u32] (16 used k-pairs + pad); B smem transposed
// [128 n][20 u32] (k-pairs). Fragment LDS is conflict-free (stride 20).
// SPLIT=1 -> write hi/lo split words; SPLIT=0 -> write fp32.
// ---------------------------------------------------------------------------
template <int SPLIT>
__global__ __launch_bounds__(256) void gemm3(
    const u32* __restrict__ Ah, const u32* __restrict__ Al,
    const u32* __restrict__ Bh, const u32* __restrict__ Bl,
    const float* __restrict__ bias,
    float* __restrict__ Cf, u32* __restrict__ Ch, u32* __restrict__ Cl,
    int M, int N, int K)
{
    __shared__ u32 sAh[128 * 20], sAl[128 * 20];
    __shared__ u32 sBh[128 * 20], sBl[128 * 20];

    const int tid = threadIdx.x;
    const int lane = tid & 31, wid = tid >> 5;
    const int t = lane & 3, gsub = lane >> 2;
    const int wm = wid >> 1, wn = wid & 1;
    const int row0 = blockIdx.y * 128, col0 = blockIdx.x * 128;
    const int Kw = K >> 1, Nw = N >> 1;

    float acc[2][8][4];
#pragma unroll
    for (int mi = 0; mi < 2; mi++)
#pragma unroll
        for (int j = 0; j < 8; j++)
#pragma unroll
            for (int e = 0; e < 4; e++) acc[mi][j][e] = 0.0f;

    for (int k0 = 0; k0 < K; k0 += 32) {
        __syncthreads();
        // A tile: 128 rows x 16 k-pair words, hi+lo. 512 uint4 units each.
#pragma unroll
        for (int i = 0; i < 2; i++) {
            int u = tid + 256 * i;
            int r = u >> 2, q = u & 3;
            size_t off = (size_t)(row0 + r) * Kw + (k0 >> 1) + q * 4;
            *(uint4*)&sAh[r * 20 + q * 4] = *(const uint4*)&Ah[off];
            *(uint4*)&sAl[r * 20 + q * 4] = *(const uint4*)&Al[off];
        }
        // B tile transposed: units (kk 0..15, np 0..63)
#pragma unroll
        for (int i = 0; i < 4; i++) {
            int u = tid + 256 * i;
            int np = u & 63, kk = u >> 6;
            size_t base = (size_t)(k0 + 2 * kk) * Nw + (col0 >> 1) + np;
            u32 wa = Bh[base], wb = Bh[base + Nw];
            sBh[(2 * np) * 20 + kk]     = __byte_perm(wa, wb, 0x5410);
            sBh[(2 * np + 1) * 20 + kk] = __byte_perm(wa, wb, 0x7632);
            wa = Bl[base]; wb = Bl[base + Nw];
            sBl[(2 * np) * 20 + kk]     = __byte_perm(wa, wb, 0x5410);
            sBl[(2 * np + 1) * 20 + kk] = __byte_perm(wa, wb, 0x7632);
        }
        __syncthreads();

#pragma unroll
        for (int ks = 0; ks < 2; ks++) {
            u32 ah[2][4], al[2][4];
#pragma unroll
            for (int mi = 0; mi < 2; mi++) {
                int rb = (wm * 32 + mi * 16 + gsub) * 20 + ks * 8 + t;
                ah[mi][0] = sAh[rb];       ah[mi][1] = sAh[rb + 160];
                ah[mi][2] = sAh[rb + 4];   ah[mi][3] = sAh[rb + 164];
                al[mi][0] = sAl[rb];       al[mi][1] = sAl[rb + 160];
                al[mi][2] = sAl[rb + 4];   al[mi][3] = sAl[rb + 164];
            }
#pragma unroll
            for (int j = 0; j < 8; j++) {
                int nb = (wn * 64 + j * 8 + gsub) * 20 + ks * 8 + t;
                u32 bh0 = sBh[nb], bh1 = sBh[nb + 4];
                u32 bl0 = sBl[nb], bl1 = sBl[nb + 4];
#pragma unroll
                for (int mi = 0; mi < 2; mi++) {
                    mma_bf16(acc[mi][j], ah[mi], bh0, bh1);
                    mma_bf16(acc[mi][j], al[mi], bh0, bh1);
                    mma_bf16(acc[mi][j], ah[mi], bl0, bl1);
                }
            }
        }
    }

    // Epilogue
#pragma unroll
    for (int mi = 0; mi < 2; mi++) {
#pragma unroll
        for (int j = 0; j < 8; j++) {
            int r = row0 + wm * 32 + mi * 16 + gsub;
            int c = col0 + wn * 64 + j * 8 + t * 2;
            float b0 = bias[c], b1 = bias[c + 1];
            float v0 = acc[mi][j][0] + b0, v1 = acc[mi][j][1] + b1;
            float v2 = acc[mi][j][2] + b0, v3 = acc[mi][j][3] + b1;
            if (SPLIT) {
                u32 hw, lw;
                size_t wi = (size_t)r * Nw + (c >> 1);
                split2(v0, v1, hw, lw); Ch[wi] = hw; Cl[wi] = lw;
                wi = (size_t)(r + 8) * Nw + (c >> 1);
                split2(v2, v3, hw, lw); Ch[wi] = hw; Cl[wi] = lw;
            } else {
                float2 o0 = {v0, v1}, o1 = {v2, v3};
                *(float2*)&Cf[(size_t)r * N + c] = o0;
                *(float2*)&Cf[(size_t)(r + 8) * N + c] = o1;
            }
        }
    }
}

// ---------------------------------------------------------------------------
// FlashAttention on tensor cores, causal, split-bf16 3-term.
// Grid (S/64, B*H), 128 threads (4 warps). Warp w owns q rows w*16..w*16+15.
// Reads split qkv words; writes split ctx words ([B,H,S,D] flat).
// Dynamic smem: Qh,Ql,Kh,Kl,Vh,Vl each [64][36] u32 = 55296 B.
// ---------------------------------------------------------------------------
#define FL_SMEM (6 * 64 * 36 * 4)

__global__ __launch_bounds__(128) void flash3(
    const u32* __restrict__ qh, const u32* __restrict__ ql,
    u32* __restrict__ ch, u32* __restrict__ cl)
{
    extern __shared__ u32 sm[];
    u32* Qh = sm;            u32* Ql = sm + 2304;
    u32* Kh = sm + 4608;     u32* Kl = sm + 6912;
    u32* Vh = sm + 9216;     u32* Vl = sm + 11520;

    const int tid = threadIdx.x;
    const int lane = tid & 31, wid = tid >> 5;
    const int t = lane & 3, gsub = lane >> 2;
    const int bh = blockIdx.y, qt = blockIdx.x, q0 = qt * 64;
    const int b = bh >> 4, h = bh & 15;
    const size_t hw0 = (size_t)h * 96;

#define ROWOFF(s_) ((size_t)(b * SS + (s_)) * NW3 + hw0)

    // Load Q tile (hi/lo): 1024 uint4 units
#pragma unroll
    for (int i = 0; i < 8; i++) {
        int u = tid + 128 * i;
        int quad = u & 7, row = (u >> 3) & 63, hl = u >> 9;
        const u32* src = (hl ? ql : qh) + ROWOFF(q0 + row) + quad * 4;
        u32* dst = (hl ? Ql : Qh) + row * 36 + quad * 4;
        *(uint4*)dst = *(const uint4*)src;
    }
    __syncthreads();

    // Hoist Q fragments (row = wid*16 + gsub)
    u32 aqh[4][4], aql[4][4];
#pragma unroll
    for (int ks = 0; ks < 4; ks++) {
        int rb = (wid * 16 + gsub) * 36 + ks * 8 + t;
        aqh[ks][0] = Qh[rb];     aqh[ks][1] = Qh[rb + 288];
        aqh[ks][2] = Qh[rb + 4]; aqh[ks][3] = Qh[rb + 292];
        aql[ks][0] = Ql[rb];     aql[ks][1] = Ql[rb + 288];
        aql[ks][2] = Ql[rb + 4]; aql[ks][3] = Ql[rb + 292];
    }

    float m0 = -1e30f, m1 = -1e30f, l0 = 0.0f, l1 = 0.0f;
    float o[8][4];
#pragma unroll
    for (int j = 0; j < 8; j++)
#pragma unroll
        for (int e = 0; e < 4; e++) o[j][e] = 0.0f;

    for (int kt = 0; kt <= qt; kt++) {
        const int k0 = kt * 64;
        __syncthreads();   // all warps done with previous K/V

        // K tile (hi/lo), natural layout [key][dpair]
#pragma unroll
        for (int i = 0; i < 8; i++) {
            int u = tid + 128 * i;
            int quad = u & 7, row = (u >> 3) & 63, hl = u >> 9;
            const u32* src = (hl ? ql : qh) + ROWOFF(k0 + row) + 32 + quad * 4;
            u32* dst = (hl ? Kl : Kh) + row * 36 + quad * 4;
            *(uint4*)dst = *(const uint4*)src;
        }
        // V tile transposed into [d][keypair] via byte_perm
#pragma unroll
        for (int hl = 0; hl < 2; hl++) {
            const u32* vsrc = (hl ? ql : qh);
            u32* vd = (hl ? Vl : Vh);
#pragma unroll
            for (int i = 0; i < 4; i++) {
                int u = tid + 128 * i;
                int dq = u & 15, k2 = u >> 4;
                uint2 a  = *(const uint2*)&vsrc[ROWOFF(k0 + 2 * k2) + 64 + dq * 2];
                uint2 bb = *(const uint2*)&vsrc[ROWOFF(k0 + 2 * k2 + 1) + 64 + dq * 2];
                vd[(4 * dq + 0) * 36 + k2] = __byte_perm(a.x, bb.x, 0x5410);
                vd[(4 * dq + 1) * 36 + k2] = __byte_perm(a.x, bb.x, 0x7632);
                vd[(4 * dq + 2) * 36 + k2] = __byte_perm(a.y, bb.y, 0x5410);
                vd[(4 * dq + 3) * 36 + k2] = __byte_perm(a.y, bb.y, 0x7632);
            }
        }
        __syncthreads();

        // Scores S = Q @ K^T (3-term)
        float s[8][4];
#pragma unroll
        for (int j = 0; j < 8; j++)
#pragma unroll
            for (int e = 0; e < 4; e++) s[j][e] = 0.0f;

#pragma unroll
        for (int ks = 0; ks < 4; ks++) {
#pragma unroll
            for (int j = 0; j < 8; j++) {
                int nb = (j * 8 + gsub) * 36 + ks * 8 + t;
                u32 kh0 = Kh[nb], kh1 = Kh[nb + 4];
                u32 kl0 = Kl[nb], kl1 = Kl[nb + 4];
                mma_bf16(s[j], aqh[ks], kh0, kh1);
                mma_bf16(s[j], aql[ks], kh0, kh1);
                mma_bf16(s[j], aqh[ks], kl0, kl1);
            }
        }

#pragma unroll
        for (int j = 0; j < 8; j++)
#pragma unroll
            for (int e = 0; e < 4; e++) s[j][e] *= 0.125f;

        if (kt == qt) {
            const int r0g = q0 + wid * 16 + gsub;
            const int r1g = r0g + 8;
#pragma unroll
            for (int j = 0; j < 8; j++) {
                int c0 = k0 + j * 8 + 2 * t;
                if (c0 > r0g)     s[j][0] = -1e30f;
                if (c0 + 1 > r0g) s[j][1] = -1e30f;
                if (c0 > r1g)     s[j][2] = -1e30f;
                if (c0 + 1 > r1g) s[j][3] = -1e30f;
            }
        }

        // Online softmax (quad-local reductions: lanes 4g..4g+3 share rows)
        float mt0 = -1e30f, mt1 = -1e30f;
#pragma unroll
        for (int j = 0; j < 8; j++) {
            mt0 = fmaxf(mt0, fmaxf(s[j][0], s[j][1]));
            mt1 = fmaxf(mt1, fmaxf(s[j][2], s[j][3]));
        }
        mt0 = fmaxf(mt0, __shfl_xor_sync(0xffffffffu, mt0, 1));
        mt0 = fmaxf(mt0, __shfl_xor_sync(0xffffffffu, mt0, 2));
        mt1 = fmaxf(mt1, __shfl_xor_sync(0xffffffffu, mt1, 1));
        mt1 = fmaxf(mt1, __shfl_xor_sync(0xffffffffu, mt1, 2));

        float mn0 = fmaxf(m0, mt0), mn1 = fmaxf(m1, mt1);
        float al0 = __expf(m0 - mn0), al1 = __expf(m1 - mn1);
        float rs0 = 0.0f, rs1 = 0.0f;
#pragma unroll
        for (int j = 0; j < 8; j++) {
            s[j][0] = __expf(s[j][0] - mn0);
            s[j][1] = __expf(s[j][1] - mn0);
            s[j][2] = __expf(s[j][2] - mn1);
            s[j][3] = __expf(s[j][3] - mn1);
            rs0 += s[j][0] + s[j][1];
            rs1 += s[j][2] + s[j][3];
        }
        rs0 += __shfl_xor_sync(0xffffffffu, rs0, 1);
        rs0 += __shfl_xor_sync(0xffffffffu, rs0, 2);
        rs1 += __shfl_xor_sync(0xffffffffu, rs1, 1);
        rs1 += __shfl_xor_sync(0xffffffffu, rs1, 2);

        l0 = l0 * al0 + rs0;  l1 = l1 * al1 + rs1;
        m0 = mn0;             m1 = mn1;
#pragma unroll
        for (int j = 0; j < 8; j++) {
            o[j][0] *= al0; o[j][1] *= al0;
            o[j][2] *= al1; o[j][3] *= al1;
        }

        // O += P @ V : score C-frag layout == PV A-frag layout (in-register)
#pragma unroll
        for (int kk = 0; kk < 4; kk++) {
            u32 ph[4], pl[4];
            split2(s[2 * kk][0],     s[2 * kk][1],     ph[0], pl[0]);
            split2(s[2 * kk][2],     s[2 * kk][3],     ph[1], pl[1]);
            split2(s[2 * kk + 1][0], s[2 * kk + 1][1], ph[2], pl[2]);
            split2(s[2 * kk + 1][2], s[2 * kk + 1][3], ph[3], pl[3]);
#pragma unroll
            for (int j = 0; j < 8; j++) {
                int nb = (j * 8 + gsub) * 36 + kk * 8 + t;
                u32 vh0 = Vh[nb], vh1 = Vh[nb + 4];
                u32 vl0 = Vl[nb], vl1 = Vl[nb + 4];
                mma_bf16(o[j], ph, vh0, vh1);
                mma_bf16(o[j], pl, vh0, vh1);
                mma_bf16(o[j], ph, vl0, vl1);
            }
        }
    }

    // Epilogue: normalize, split, store to ctx [B,H,S,D]-flat (32 words/row)
    const float i0 = 1.0f / l0, i1 = 1.0f / l1;
    const size_t orow = ((size_t)bh * SS + q0 + wid * 16 + gsub) * 32;
#pragma unroll
    for (int j = 0; j < 8; j++) {
        int wc = 4 * j + t;
        u32 hw, lw;
        split2(o[j][0] * i0, o[j][1] * i0, hw, lw);
        ch[orow + wc] = hw;  cl[orow + wc] = lw;
        split2(o[j][2] * i1, o[j][3] * i1, hw, lw);
        ch[orow + 256 + wc] = hw;  cl[orow + 256 + wc] = lw;  // +8 rows * 32 words
    }
#undef ROWOFF
}

// ---------------------------------------------------------------------------
// Launch
// ---------------------------------------------------------------------------
extern "C" void kernel_launch(void* const* d_in, const int* in_sizes, int n_in,
                              void* d_out, int out_size)
{
    const float* x    = (const float*)d_in[0];
    // d_in[1] = causal mask (tril -> handled analytically)
    const float* Wqkv = (const float*)d_in[2];
    const float* bqkv = (const float*)d_in[3];
    const float* Wo   = (const float*)d_in[4];
    const float* bo   = (const float*)d_in[5];
    float* out = (float*)d_out;

    u32 *xh, *xl, *wqh, *wql, *woh, *wol, *qkvh, *qkvl, *ctxh, *ctxl;
    cudaGetSymbolAddress((void**)&xh, g_xh);
    cudaGetSymbolAddress((void**)&xl, g_xl);
    cudaGetSymbolAddress((void**)&wqh, g_wqh);
    cudaGetSymbolAddress((void**)&wql, g_wql);
    cudaGetSymbolAddress((void**)&woh, g_woh);
    cudaGetSymbolAddress((void**)&wol, g_wol);
    cudaGetSymbolAddress((void**)&qkvh, g_qkvh);
    cudaGetSymbolAddress((void**)&qkvl, g_qkvl);
    cudaGetSymbolAddress((void**)&ctxh, g_ctxh);
    cudaGetSymbolAddress((void**)&ctxl, g_ctxl);

    cudaFuncSetAttribute(flash3, cudaFuncAttributeMaxDynamicSharedMemorySize,
                         FL_SMEM);

    // 0) split inputs
    {
        int nx = NROWS * EW;      // 4,194,304
        int nq = EE * NW3;        // 1,572,864
        int no = EE * EW;         // 524,288
        split_kernel<<<(nx + 255) / 256, 256>>>(x, xh, xl, nx);
        split_kernel<<<(nq + 255) / 256, 256>>>(Wqkv, wqh, wql, nq);
        split_kernel<<<(no + 255) / 256, 256>>>(Wo, woh, wol, no);
    }
    // 1) QKV projection -> split qkv
    {
        dim3 grid(K3E / 128, NROWS / 128);   // (24, 64)
        gemm3<1><<<grid, 256>>>(xh, xl, wqh, wql, bqkv,
                                nullptr, qkvh, qkvl, NROWS, K3E, EE);
    }
    // 2) Causal flash attention -> split ctx
    {
        dim3 grid(SS / 64, BB * HH);         // (32, 64)
        flash3<<<grid, 128, FL_SMEM>>>(qkvh, qkvl, ctxh, ctxl);
    }
    // 3) Output projection -> fp32 out
    {
        dim3 grid(EE / 128, NROWS / 128);    // (8, 64)
        gemm3<0><<<grid, 256>>>(ctxh, ctxl, woh, wol, bo,
                                out, nullptr, nullptr, NROWS, EE, EE);
    }
}

// round 12
// speedup vs baseline: 3.6088x; 1.3011x over previous
#include <cuda_runtime.h>
#include <cuda_bf16.h>
#include <math.h>

typedef unsigned int u32;

#define BB 4
#define SS 2048
#define EE 1024
#define HH 16
#define DD 64
#define NROWS 8192
#define K3E 3072
#define NW3 1536   // words per qkv row (K3E/2)
#define EW  512    // words per E row (EE/2)

// ---------------------------------------------------------------------------
// Scratch: hi/lo split bf16 word buffers
// ---------------------------------------------------------------------------
__device__ u32 g_xh[(size_t)NROWS * EW];
__device__ u32 g_xl[(size_t)NROWS * EW];
__device__ u32 g_wqh[(size_t)K3E * EW];   // Wqkv^T: [3072][512] k-pair words
__device__ u32 g_wql[(size_t)K3E * EW];
__device__ u32 g_woh[(size_t)EE * EW];    // Wo^T:   [1024][512]
__device__ u32 g_wol[(size_t)EE * EW];
__device__ u32 g_qkvh[(size_t)NROWS * NW3];
__device__ u32 g_qkvl[(size_t)NROWS * NW3];
__device__ u32 g_ctxh[(size_t)NROWS * EW];
__device__ u32 g_ctxl[(size_t)NROWS * EW];

// ---------------------------------------------------------------------------
// Helpers
// ---------------------------------------------------------------------------
__device__ __forceinline__ void split2(float x, float y, u32& h, u32& l) {
    __nv_bfloat162 hb = __floats2bfloat162_rn(x, y);   // .x = x (low 16 bits)
    h = *reinterpret_cast<u32*>(&hb);
    float rx = x - __bfloat162float(hb.x);
    float ry = y - __bfloat162float(hb.y);
    __nv_bfloat162 lb = __floats2bfloat162_rn(rx, ry);
    l = *reinterpret_cast<u32*>(&lb);
}

__device__ __forceinline__ void mma_bf16(float* c, const u32* a, u32 b0, u32 b1) {
    asm volatile(
        "mma.sync.aligned.m16n8k16.row.col.f32.bf16.bf16.f32 "
        "{%0,%1,%2,%3}, {%4,%5,%6,%7}, {%8,%9}, {%0,%1,%2,%3};"
        : "+f"(c[0]), "+f"(c[1]), "+f"(c[2]), "+f"(c[3])
        : "r"(a[0]), "r"(a[1]), "r"(a[2]), "r"(a[3]), "r"(b0), "r"(b1));
}

__device__ __forceinline__ void cpasync16(u32* dst, const u32* src) {
    u32 d = (u32)__cvta_generic_to_shared(dst);
    asm volatile("cp.async.cg.shared.global [%0], [%1], 16;" :: "r"(d), "l"(src));
}
__device__ __forceinline__ void cp_commit() {
    asm volatile("cp.async.commit_group;");
}
template <int N>
__device__ __forceinline__ void cp_wait() {
    asm volatile("cp.async.wait_group %0;" :: "n"(N));
}

// ---------------------------------------------------------------------------
// Split fp32 array -> hi/lo bf16 word arrays (pairwise)
// ---------------------------------------------------------------------------
__global__ void split_kernel(const float* __restrict__ in,
                             u32* __restrict__ h, u32* __restrict__ l,
                             int nwords) {
    int i = blockIdx.x * 256 + threadIdx.x;
    if (i < nwords) {
        float2 v = ((const float2*)in)[i];
        u32 hw, lw;
        split2(v.x, v.y, hw, lw);
        h[i] = hw;
        l[i] = lw;
    }
}

// ---------------------------------------------------------------------------
// Split + transpose weights: in[K][N] fp32 -> out[n][kp] = pack(in[2kp][n],
// in[2kp+1][n]) hi/lo. Consecutive threads share kp, walk n -> coalesced reads.
// ---------------------------------------------------------------------------
__global__ void splitT_kernel(const float* __restrict__ in,
                              u32* __restrict__ h, u32* __restrict__ l,
                              int N, int K) {
    int idx = blockIdx.x * 256 + threadIdx.x;
    int Kw = K >> 1;
    if (idx >= N * Kw) return;
    int n = idx % N;
    int kp = idx / N;
    float x = in[(size_t)(2 * kp) * N + n];
    float y = in[(size_t)(2 * kp + 1) * N + n];
    u32 hw, lw;
    split2(x, y, hw, lw);
    h[(size_t)n * Kw + kp] = hw;
    l[(size_t)n * Kw + kp] = lw;
}

// ---------------------------------------------------------------------------
// GEMM bf16x3 with cp.async double-buffering.
// C[M,N] = (Ah+Al)[M,K] @ (Bth+Btl)^T + bias, Bt given pretransposed [N][Kw].
// 128x128x32 tile, 256 threads (8 warps, warp tile 32x64).
// Dynamic smem: 2 stages x 4 arrays x [128][20] u32 = 81920 B.
// SPLIT=1 -> hi/lo split word output; SPLIT=0 -> fp32 output.
// ---------------------------------------------------------------------------
#define GST 2560            // words per array per stage (128*20)
#define GEMM_SMEM (2 * 4 * GST * 4)

template <int SPLIT>
__global__ __launch_bounds__(256) void gemm3(
    const u32* __restrict__ Ah, const u32* __restrict__ Al,
    const u32* __restrict__ Bth, const u32* __restrict__ Btl,
    const float* __restrict__ bias,
    float* __restrict__ Cf, u32* __restrict__ Ch, u32* __restrict__ Cl,
    int M, int N, int K)
{
    extern __shared__ u32 smw[];

    const int tid = threadIdx.x;
    const int lane = tid & 31, wid = tid >> 5;
    const int t = lane & 3, gsub = lane >> 2;
    const int wm = wid >> 1, wn = wid & 1;
    const int row0 = blockIdx.y * 128, col0 = blockIdx.x * 128;
    const int Kw = K >> 1, Nw = N >> 1;

    const int ldr = tid >> 2;          // 0..63  (2 chunks each -> 128 rows)
    const int ldq = tid & 3;           // quad within row

    float acc[2][8][4];
#pragma unroll
    for (int mi = 0; mi < 2; mi++)
#pragma unroll
        for (int j = 0; j < 8; j++)
#pragma unroll
            for (int e = 0; e < 4; e++) acc[mi][j][e] = 0.0f;

#define LOAD_STAGE(s_, k0_) do {                                              \
    u32* bse = smw + (s_) * 4 * GST;                                          \
    int kwo = (k0_) >> 1;                                                     \
    _Pragma("unroll")                                                         \
    for (int i_ = 0; i_ < 2; i_++) {                                          \
        int r_ = ldr + 64 * i_;                                               \
        size_t ga = (size_t)(row0 + r_) * Kw + kwo + ldq * 4;                 \
        size_t gb = (size_t)(col0 + r_) * Kw + kwo + ldq * 4;                 \
        int so = r_ * 20 + ldq * 4;                                           \
        cpasync16(bse + so,           (u32*)(Ah  + ga));                      \
        cpasync16(bse + GST + so,     (u32*)(Al  + ga));                      \
        cpasync16(bse + 2 * GST + so, (u32*)(Bth + gb));                      \
        cpasync16(bse + 3 * GST + so, (u32*)(Btl + gb));                      \
    } } while (0)

    const int T = K >> 5;   // 32-wide k tiles
    LOAD_STAGE(0, 0);
    cp_commit();

    for (int it = 0; it < T; it++) {
        if (it + 1 < T) {
            LOAD_STAGE((it + 1) & 1, (it + 1) * 32);
            cp_commit();
            cp_wait<1>();
        } else {
            cp_wait<0>();
        }
        __syncthreads();

        u32* bse = smw + (it & 1) * 4 * GST;
        u32* sAh = bse;
        u32* sAl = bse + GST;
        u32* sBh = bse + 2 * GST;
        u32* sBl = bse + 3 * GST;

#pragma unroll
        for (int ks = 0; ks < 2; ks++) {
            u32 ah[2][4], al[2][4];
#pragma unroll
            for (int mi = 0; mi < 2; mi++) {
                int rb = (wm * 32 + mi * 16 + gsub) * 20 + ks * 8 + t;
                ah[mi][0] = sAh[rb];       ah[mi][1] = sAh[rb + 160];
                ah[mi][2] = sAh[rb + 4];   ah[mi][3] = sAh[rb + 164];
                al[mi][0] = sAl[rb];       al[mi][1] = sAl[rb + 160];
                al[mi][2] = sAl[rb + 4];   al[mi][3] = sAl[rb + 164];
            }
#pragma unroll
            for (int j = 0; j < 8; j++) {
                int nb = (wn * 64 + j * 8 + gsub) * 20 + ks * 8 + t;
                u32 bh0 = sBh[nb], bh1 = sBh[nb + 4];
                u32 bl0 = sBl[nb], bl1 = sBl[nb + 4];
#pragma unroll
                for (int mi = 0; mi < 2; mi++) {
                    mma_bf16(acc[mi][j], ah[mi], bh0, bh1);
                    mma_bf16(acc[mi][j], al[mi], bh0, bh1);
                    mma_bf16(acc[mi][j], ah[mi], bl0, bl1);
                }
            }
        }
        __syncthreads();
    }
#undef LOAD_STAGE

    // Epilogue
#pragma unroll
    for (int mi = 0; mi < 2; mi++) {
#pragma unroll
        for (int j = 0; j < 8; j++) {
            int r = row0 + wm * 32 + mi * 16 + gsub;
            int c = col0 + wn * 64 + j * 8 + t * 2;
            float b0 = bias[c], b1 = bias[c + 1];
            float v0 = acc[mi][j][0] + b0, v1 = acc[mi][j][1] + b1;
            float v2 = acc[mi][j][2] + b0, v3 = acc[mi][j][3] + b1;
            if (SPLIT) {
                u32 hw, lw;
                size_t wi = (size_t)r * Nw + (c >> 1);
                split2(v0, v1, hw, lw); Ch[wi] = hw; Cl[wi] = lw;
                wi = (size_t)(r + 8) * Nw + (c >> 1);
                split2(v2, v3, hw, lw); Ch[wi] = hw; Cl[wi] = lw;
            } else {
                float2 o0 = {v0, v1}, o1 = {v2, v3};
                *(float2*)&Cf[(size_t)r * N + c] = o0;
                *(float2*)&Cf[(size_t)(r + 8) * N + c] = o1;
            }
        }
    }
}

// ---------------------------------------------------------------------------
// FlashAttention on tensor cores, causal, split-bf16 3-term.
// Q tile 128 rows, 8 warps (256 thr); K/V tiles 64 wide.
// Grid (S/128, B*H). Dynamic smem: Q 2x[128][36] + K,V 4x[64][36] = 73728 B.
// ---------------------------------------------------------------------------
#define FL_SMEM ((2 * 128 * 36 + 4 * 64 * 36) * 4)

__global__ __launch_bounds__(256) void flash3(
    const u32* __restrict__ qh, const u32* __restrict__ ql,
    u32* __restrict__ ch, u32* __restrict__ cl)
{
    extern __shared__ u32 sm[];
    u32* Qh = sm;             // [128][36]
    u32* Ql = sm + 4608;
    u32* Kh = sm + 9216;      // [64][36]
    u32* Kl = sm + 11520;
    u32* Vh = sm + 13824;     // [64][36] (transposed: [d][keypair])
    u32* Vl = sm + 16128;

    const int tid = threadIdx.x;
    const int lane = tid & 31, wid = tid >> 5;
    const int t = lane & 3, gsub = lane >> 2;
    const int bh = blockIdx.y, qt = blockIdx.x, q0 = qt * 128;
    const int b = bh >> 4, h = bh & 15;
    const size_t hw0 = (size_t)h * 96;

#define ROWOFF(s_) ((size_t)(b * SS + (s_)) * NW3 + hw0)

    // Load Q tile (hi/lo): 2048 uint4 units
#pragma unroll
    for (int i = 0; i < 8; i++) {
        int u = tid + 256 * i;
        int quad = u & 7, row = (u >> 3) & 127, hl = u >> 10;
        const u32* src = (hl ? ql : qh) + ROWOFF(q0 + row) + quad * 4;
        u32* dst = (hl ? Ql : Qh) + row * 36 + quad * 4;
        *(uint4*)dst = *(const uint4*)src;
    }
    __syncthreads();

    // Hoist Q fragments (warp rows: q0 + wid*16 + gsub, +8)
    u32 aqh[4][4], aql[4][4];
#pragma unroll
    for (int ks = 0; ks < 4; ks++) {
        int rb = (wid * 16 + gsub) * 36 + ks * 8 + t;
        aqh[ks][0] = Qh[rb];     aqh[ks][1] = Qh[rb + 288];
        aqh[ks][2] = Qh[rb + 4]; aqh[ks][3] = Qh[rb + 292];
        aql[ks][0] = Ql[rb];     aql[ks][1] = Ql[rb + 288];
        aql[ks][2] = Ql[rb + 4]; aql[ks][3] = Ql[rb + 292];
    }

    float m0 = -1e30f, m1 = -1e30f, l0 = 0.0f, l1 = 0.0f;
    float o[8][4];
#pragma unroll
    for (int j = 0; j < 8; j++)
#pragma unroll
        for (int e = 0; e < 4; e++) o[j][e] = 0.0f;

    const int nkt = 2 * qt + 2;
    for (int kt = 0; kt < nkt; kt++) {
        const int k0 = kt * 64;
        __syncthreads();

        // K tile (hi/lo): 1024 uint4 units
#pragma unroll
        for (int i = 0; i < 4; i++) {
            int u = tid + 256 * i;
            int quad = u & 7, row = (u >> 3) & 63, hl = u >> 9;
            const u32* src = (hl ? ql : qh) + ROWOFF(k0 + row) + 32 + quad * 4;
            u32* dst = (hl ? Kl : Kh) + row * 36 + quad * 4;
            *(uint4*)dst = *(const uint4*)src;
        }
        // V tile transposed [d][keypair] via byte_perm
#pragma unroll
        for (int hl = 0; hl < 2; hl++) {
            const u32* vsrc = (hl ? ql : qh);
            u32* vd = (hl ? Vl : Vh);
#pragma unroll
            for (int i = 0; i < 2; i++) {
                int u = tid + 256 * i;
                int dq = u & 15, k2 = u >> 4;
                uint2 a  = *(const uint2*)&vsrc[ROWOFF(k0 + 2 * k2) + 64 + dq * 2];
                uint2 bb = *(const uint2*)&vsrc[ROWOFF(k0 + 2 * k2 + 1) + 64 + dq * 2];
                vd[(4 * dq + 0) * 36 + k2] = __byte_perm(a.x, bb.x, 0x5410);
                vd[(4 * dq + 1) * 36 + k2] = __byte_perm(a.x, bb.x, 0x7632);
                vd[(4 * dq + 2) * 36 + k2] = __byte_perm(a.y, bb.y, 0x5410);
                vd[(4 * dq + 3) * 36 + k2] = __byte_perm(a.y, bb.y, 0x7632);
            }
        }
        __syncthreads();

        // Scores S = Q @ K^T (3-term)
        float s[8][4];
#pragma unroll
        for (int j = 0; j < 8; j++)
#pragma unroll
            for (int e = 0; e < 4; e++) s[j][e] = 0.0f;

#pragma unroll
        for (int ks = 0; ks < 4; ks++) {
#pragma unroll
            for (int j = 0; j < 8; j++) {
                int nb = (j * 8 + gsub) * 36 + ks * 8 + t;
                u32 kh0 = Kh[nb], kh1 = Kh[nb + 4];
                u32 kl0 = Kl[nb], kl1 = Kl[nb + 4];
                mma_bf16(s[j], aqh[ks], kh0, kh1);
                mma_bf16(s[j], aql[ks], kh0, kh1);
                mma_bf16(s[j], aqh[ks], kl0, kl1);
            }
        }

#pragma unroll
        for (int j = 0; j < 8; j++)
#pragma unroll
            for (int e = 0; e < 4; e++) s[j][e] *= 0.125f;

        if (kt >= 2 * qt) {   // diagonal region
            const int r0g = q0 + wid * 16 + gsub;
            const int r1g = r0g + 8;
#pragma unroll
            for (int j = 0; j < 8; j++) {
                int c0 = k0 + j * 8 + 2 * t;
                if (c0 > r0g)     s[j][0] = -1e30f;
                if (c0 + 1 > r0g) s[j][1] = -1e30f;
                if (c0 > r1g)     s[j][2] = -1e30f;
                if (c0 + 1 > r1g) s[j][3] = -1e30f;
            }
        }

        // Online softmax (quad-local reductions)
        float mt0 = -1e30f, mt1 = -1e30f;
#pragma unroll
        for (int j = 0; j < 8; j++) {
            mt0 = fmaxf(mt0, fmaxf(s[j][0], s[j][1]));
            mt1 = fmaxf(mt1, fmaxf(s[j][2], s[j][3]));
        }
        mt0 = fmaxf(mt0, __shfl_xor_sync(0xffffffffu, mt0, 1));
        mt0 = fmaxf(mt0, __shfl_xor_sync(0xffffffffu, mt0, 2));
        mt1 = fmaxf(mt1, __shfl_xor_sync(0xffffffffu, mt1, 1));
        mt1 = fmaxf(mt1, __shfl_xor_sync(0xffffffffu, mt1, 2));

        float mn0 = fmaxf(m0, mt0), mn1 = fmaxf(m1, mt1);
        float al0 = __expf(m0 - mn0), al1 = __expf(m1 - mn1);
        float rs0 = 0.0f, rs1 = 0.0f;
#pragma unroll
        for (int j = 0; j < 8; j++) {
            s[j][0] = __expf(s[j][0] - mn0);
            s[j][1] = __expf(s[j][1] - mn0);
            s[j][2] = __expf(s[j][2] - mn1);
            s[j][3] = __expf(s[j][3] - mn1);
            rs0 += s[j][0] + s[j][1];
            rs1 += s[j][2] + s[j][3];
        }
        rs0 += __shfl_xor_sync(0xffffffffu, rs0, 1);
        rs0 += __shfl_xor_sync(0xffffffffu, rs0, 2);
        rs1 += __shfl_xor_sync(0xffffffffu, rs1, 1);
        rs1 += __shfl_xor_sync(0xffffffffu, rs1, 2);

        l0 = l0 * al0 + rs0;  l1 = l1 * al1 + rs1;
        m0 = mn0;             m1 = mn1;
#pragma unroll
        for (int j = 0; j < 8; j++) {
            o[j][0] *= al0; o[j][1] *= al0;
            o[j][2] *= al1; o[j][3] *= al1;
        }

        // O += P @ V (P stays in registers: score C-frag == PV A-frag)
#pragma unroll
        for (int kk = 0; kk < 4; kk++) {
            u32 ph[4], pl[4];
            split2(s[2 * kk][0],     s[2 * kk][1],     ph[0], pl[0]);
            split2(s[2 * kk][2],     s[2 * kk][3],     ph[1], pl[1]);
            split2(s[2 * kk + 1][0], s[2 * kk + 1][1], ph[2], pl[2]);
            split2(s[2 * kk + 1][2], s[2 * kk + 1][3], ph[3], pl[3]);
#pragma unroll
            for (int j = 0; j < 8; j++) {
                int nb = (j * 8 + gsub) * 36 + kk * 8 + t;
                u32 vh0 = Vh[nb], vh1 = Vh[nb + 4];
                u32 vl0 = Vl[nb], vl1 = Vl[nb + 4];
                mma_bf16(o[j], ph, vh0, vh1);
                mma_bf16(o[j], pl, vh0, vh1);
                mma_bf16(o[j], ph, vl0, vl1);
            }
        }
    }

    // Epilogue: normalize, split, store to ctx [B,H,S,D]-flat (32 words/row)
    const float i0 = 1.0f / l0, i1 = 1.0f / l1;
    const size_t orow = ((size_t)bh * SS + q0 + wid * 16 + gsub) * 32;
#pragma unroll
    for (int j = 0; j < 8; j++) {
        int wc = 4 * j + t;
        u32 hw, lw;
        split2(o[j][0] * i0, o[j][1] * i0, hw, lw);
        ch[orow + wc] = hw;  cl[orow + wc] = lw;
        split2(o[j][2] * i1, o[j][3] * i1, hw, lw);
        ch[orow + 256 + wc] = hw;  cl[orow + 256 + wc] = lw;  // +8 rows
    }
#undef ROWOFF
}

// ---------------------------------------------------------------------------
// Launch
// ---------------------------------------------------------------------------
extern "C" void kernel_launch(void* const* d_in, const int* in_sizes, int n_in,
                              void* d_out, int out_size)
{
    const float* x    = (const float*)d_in[0];
    // d_in[1] = causal mask (tril -> handled analytically)
    const float* Wqkv = (const float*)d_in[2];
    const float* bqkv = (const float*)d_in[3];
    const float* Wo   = (const float*)d_in[4];
    const float* bo   = (const float*)d_in[5];
    float* out = (float*)d_out;

    u32 *xh, *xl, *wqh, *wql, *woh, *wol, *qkvh, *qkvl, *ctxh, *ctxl;
    cudaGetSymbolAddress((void**)&xh, g_xh);
    cudaGetSymbolAddress((void**)&xl, g_xl);
    cudaGetSymbolAddress((void**)&wqh, g_wqh);
    cudaGetSymbolAddress((void**)&wql, g_wql);
    cudaGetSymbolAddress((void**)&woh, g_woh);
    cudaGetSymbolAddress((void**)&wol, g_wol);
    cudaGetSymbolAddress((void**)&qkvh, g_qkvh);
    cudaGetSymbolAddress((void**)&qkvl, g_qkvl);
    cudaGetSymbolAddress((void**)&ctxh, g_ctxh);
    cudaGetSymbolAddress((void**)&ctxl, g_ctxl);

    cudaFuncSetAttribute(gemm3<1>, cudaFuncAttributeMaxDynamicSharedMemorySize,
                         GEMM_SMEM);
    cudaFuncSetAttribute(gemm3<0>, cudaFuncAttributeMaxDynamicSharedMemorySize,
                         GEMM_SMEM);
    cudaFuncSetAttribute(flash3, cudaFuncAttributeMaxDynamicSharedMemorySize,
                         FL_SMEM);

    // 0) split inputs (x pairwise; weights transposed into k-pair layout)
    {
        int nx = NROWS * EW;            // 4,194,304 words
        int nq = K3E * EW;              // Wqkv^T words
        int no = EE * EW;               // Wo^T words
        split_kernel<<<(nx + 255) / 256, 256>>>(x, xh, xl, nx);
        splitT_kernel<<<(nq + 255) / 256, 256>>>(Wqkv, wqh, wql, K3E, EE);
        splitT_kernel<<<(no + 255) / 256, 256>>>(Wo, woh, wol, EE, EE);
    }
    // 1) QKV projection -> split qkv
    {
        dim3 grid(K3E / 128, NROWS / 128);   // (24, 64)
        gemm3<1><<<grid, 256, GEMM_SMEM>>>(xh, xl, wqh, wql, bqkv,
                                           nullptr, qkvh, qkvl,
                                           NROWS, K3E, EE);
    }
    // 2) Causal flash attention -> split ctx
    {
        dim3 grid(SS / 128, BB * HH);        // (16, 64)
        flash3<<<grid, 256, FL_SMEM>>>(qkvh, qkvl, ctxh, ctxl);
    }
    // 3) Output projection -> fp32 out
    {
        dim3 grid(EE / 128, NROWS / 128);    // (8, 64)
        gemm3<0><<<grid, 256, GEMM_SMEM>>>(ctxh, ctxl, woh, wol, bo,
                                           out, nullptr, nullptr,
                                           NROWS, EE, EE);
    }
}

// round 17
// speedup vs baseline: 4.0107x; 1.1114x over previous
#include <cuda_runtime.h>
#include <cuda_bf16.h>
#include <math.h>

typedef unsigned int u32;

#define BB 4
#define SS 2048
#define EE 1024
#define HH 16
#define DD 64
#define NROWS 8192
#define K3E 3072
#define NW3 1536   // words per qkv row (K3E/2)
#define EW  512    // words per E row (EE/2)

// ---------------------------------------------------------------------------
// Scratch: hi/lo split bf16 word buffers
// ---------------------------------------------------------------------------
__device__ u32 g_xh[(size_t)NROWS * EW];
__device__ u32 g_xl[(size_t)NROWS * EW];
__device__ u32 g_wqh[(size_t)K3E * EW];   // Wqkv^T: [3072][512] k-pair words
__device__ u32 g_wql[(size_t)K3E * EW];
__device__ u32 g_woh[(size_t)EE * EW];    // Wo^T:   [1024][512]
__device__ u32 g_wol[(size_t)EE * EW];
__device__ u32 g_qkvh[(size_t)NROWS * NW3];
__device__ u32 g_qkvl[(size_t)NROWS * NW3];
__device__ u32 g_ctxh[(size_t)NROWS * EW];
__device__ u32 g_ctxl[(size_t)NROWS * EW];

// ---------------------------------------------------------------------------
// Helpers
// ---------------------------------------------------------------------------
__device__ __forceinline__ void split2(float x, float y, u32& h, u32& l) {
    __nv_bfloat162 hb = __floats2bfloat162_rn(x, y);   // .x = x (low 16 bits)
    h = *reinterpret_cast<u32*>(&hb);
    float rx = x - __bfloat162float(hb.x);
    float ry = y - __bfloat162float(hb.y);
    __nv_bfloat162 lb = __floats2bfloat162_rn(rx, ry);
    l = *reinterpret_cast<u32*>(&lb);
}

__device__ __forceinline__ void mma_bf16(float* c, const u32* a, u32 b0, u32 b1) {
    asm volatile(
        "mma.sync.aligned.m16n8k16.row.col.f32.bf16.bf16.f32 "
        "{%0,%1,%2,%3}, {%4,%5,%6,%7}, {%8,%9}, {%0,%1,%2,%3};"
        : "+f"(c[0]), "+f"(c[1]), "+f"(c[2]), "+f"(c[3])
        : "r"(a[0]), "r"(a[1]), "r"(a[2]), "r"(a[3]), "r"(b0), "r"(b1));
}

__device__ __forceinline__ void ldsm4(u32* r, u32 addr) {
    asm volatile("ldmatrix.sync.aligned.m8n8.x4.shared.b16 {%0,%1,%2,%3}, [%4];"
                 : "=r"(r[0]), "=r"(r[1]), "=r"(r[2]), "=r"(r[3]) : "r"(addr));
}
__device__ __forceinline__ void ldsm4t(u32* r, u32 addr) {
    asm volatile("ldmatrix.sync.aligned.m8n8.x4.trans.shared.b16 {%0,%1,%2,%3}, [%4];"
                 : "=r"(r[0]), "=r"(r[1]), "=r"(r[2]), "=r"(r[3]) : "r"(addr));
}

__device__ __forceinline__ void cpasync16(u32* dst, const u32* src) {
    u32 d = (u32)__cvta_generic_to_shared(dst);
    asm volatile("cp.async.cg.shared.global [%0], [%1], 16;" :: "r"(d), "l"(src));
}
__device__ __forceinline__ void cp_commit() {
    asm volatile("cp.async.commit_group;");
}
template <int N>
__device__ __forceinline__ void cp_wait() {
    asm volatile("cp.async.wait_group %0;" :: "n"(N));
}

// ---------------------------------------------------------------------------
// Split fp32 array -> hi/lo bf16 word arrays (pairwise)
// ---------------------------------------------------------------------------
__global__ void split_kernel(const float* __restrict__ in,
                             u32* __restrict__ h, u32* __restrict__ l,
                             int nwords) {
    int i = blockIdx.x * 256 + threadIdx.x;
    if (i < nwords) {
        float2 v = ((const float2*)in)[i];
        u32 hw, lw;
        split2(v.x, v.y, hw, lw);
        h[i] = hw;
        l[i] = lw;
    }
}

// ---------------------------------------------------------------------------
// Split + transpose weights: in[K][N] fp32 -> out[n][kp]
// ---------------------------------------------------------------------------
__global__ void splitT_kernel(const float* __restrict__ in,
                              u32* __restrict__ h, u32* __restrict__ l,
                              int N, int K) {
    int idx = blockIdx.x * 256 + threadIdx.x;
    int Kw = K >> 1;
    if (idx >= N * Kw) return;
    int n = idx % N;
    int kp = idx / N;
    float x = in[(size_t)(2 * kp) * N + n];
    float y = in[(size_t)(2 * kp + 1) * N + n];
    u32 hw, lw;
    split2(x, y, hw, lw);
    h[(size_t)n * Kw + kp] = hw;
    l[(size_t)n * Kw + kp] = lw;
}

// ---------------------------------------------------------------------------
// GEMM bf16x3, cp.async double-buffered, ldmatrix fragment loads.
// C[M,N] = (Ah+Al)[M,K] @ (Bth+Btl)^T + bias, Bt pretransposed [N][Kw].
// 128x128x32 tile, 256 threads (8 warps, warp tile 32x64).
// ---------------------------------------------------------------------------
#define GST 2560            // words per array per stage (128*20)
#define GEMM_SMEM (2 * 4 * GST * 4)

template <int SPLIT>
__global__ __launch_bounds__(256) void gemm3(
    const u32* __restrict__ Ah, const u32* __restrict__ Al,
    const u32* __restrict__ Bth, const u32* __restrict__ Btl,
    const float* __restrict__ bias,
    float* __restrict__ Cf, u32* __restrict__ Ch, u32* __restrict__ Cl,
    int M, int N, int K)
{
    extern __shared__ u32 smw[];
    const u32 smbase = (u32)__cvta_generic_to_shared(smw);

    const int tid = threadIdx.x;
    const int lane = tid & 31, wid = tid >> 5;
    const int t = lane & 3, gsub = lane >> 2;
    const int wm = wid >> 1, wn = wid & 1;
    const int row0 = blockIdx.y * 128, col0 = blockIdx.x * 128;
    const int Kw = K >> 1, Nw = N >> 1;

    const int ldr = tid >> 2;          // 0..63
    const int ldq = tid & 3;

    // ldmatrix lane geometry
    const int lr = lane & 15;                 // row within 16-row block
    const u32 lc = (u32)((lane >> 4) * 16);   // 0 or 16 bytes (k halves)

    float acc[2][8][4];
#pragma unroll
    for (int mi = 0; mi < 2; mi++)
#pragma unroll
        for (int j = 0; j < 8; j++)
#pragma unroll
            for (int e = 0; e < 4; e++) acc[mi][j][e] = 0.0f;

#define LOAD_STAGE(s_, k0_) do {                                              \
    u32* bse = smw + (s_) * 4 * GST;                                          \
    int kwo = (k0_) >> 1;                                                     \
    _Pragma("unroll")                                                         \
    for (int i_ = 0; i_ < 2; i_++) {                                          \
        int r_ = ldr + 64 * i_;                                               \
        size_t ga = (size_t)(row0 + r_) * Kw + kwo + ldq * 4;                 \
        size_t gb = (size_t)(col0 + r_) * Kw + kwo + ldq * 4;                 \
        int so = r_ * 20 + ldq * 4;                                           \
        cpasync16(bse + so,           Ah  + ga);                              \
        cpasync16(bse + GST + so,     Al  + ga);                              \
        cpasync16(bse + 2 * GST + so, Bth + gb);                              \
        cpasync16(bse + 3 * GST + so, Btl + gb);                              \
    } } while (0)

    const int T = K >> 5;
    LOAD_STAGE(0, 0);
    cp_commit();

    for (int it = 0; it < T; it++) {
        if (it + 1 < T) {
            LOAD_STAGE((it + 1) & 1, (it + 1) * 32);
            cp_commit();
            cp_wait<1>();
        } else {
            cp_wait<0>();
        }
        __syncthreads();

        const u32 sb = smbase + (u32)((it & 1) * 4 * GST * 4);
        const u32 abase  = sb + (u32)((wm * 32 + lr) * 80) + lc;   // 20w=80B rows
        const u32 albase = abase + GST * 4;
        const u32 bbase  = sb + 2 * GST * 4 + (u32)((wn * 64 + lr) * 80) + lc;
        const u32 blbase = bbase + GST * 4;

#pragma unroll
        for (int ks = 0; ks < 2; ks++) {
            u32 ah[2][4], al[2][4];
            ldsm4(ah[0], abase + ks * 32);
            ldsm4(ah[1], abase + 1280 + ks * 32);
            ldsm4(al[0], albase + ks * 32);
            ldsm4(al[1], albase + 1280 + ks * 32);
#pragma unroll
            for (int u = 0; u < 4; u++) {
                u32 bh[4], bl[4];
                ldsm4(bh, bbase + u * 1280 + ks * 32);
                ldsm4(bl, blbase + u * 1280 + ks * 32);
#pragma unroll
                for (int mi = 0; mi < 2; mi++) {
                    mma_bf16(acc[mi][2 * u],     ah[mi], bh[0], bh[2]);
                    mma_bf16(acc[mi][2 * u],     al[mi], bh[0], bh[2]);
                    mma_bf16(acc[mi][2 * u],     ah[mi], bl[0], bl[2]);
                    mma_bf16(acc[mi][2 * u + 1], ah[mi], bh[1], bh[3]);
                    mma_bf16(acc[mi][2 * u + 1], al[mi], bh[1], bh[3]);
                    mma_bf16(acc[mi][2 * u + 1], ah[mi], bl[1], bl[3]);
                }
            }
        }
        __syncthreads();
    }
#undef LOAD_STAGE

    // Epilogue
#pragma unroll
    for (int mi = 0; mi < 2; mi++) {
#pragma unroll
        for (int j = 0; j < 8; j++) {
            int r = row0 + wm * 32 + mi * 16 + gsub;
            int c = col0 + wn * 64 + j * 8 + t * 2;
            float b0 = bias[c], b1 = bias[c + 1];
            float v0 = acc[mi][j][0] + b0, v1 = acc[mi][j][1] + b1;
            float v2 = acc[mi][j][2] + b0, v3 = acc[mi][j][3] + b1;
            if (SPLIT) {
                u32 hw, lw;
                size_t wi = (size_t)r * Nw + (c >> 1);
                split2(v0, v1, hw, lw); Ch[wi] = hw; Cl[wi] = lw;
                wi = (size_t)(r + 8) * Nw + (c >> 1);
                split2(v2, v3, hw, lw); Ch[wi] = hw; Cl[wi] = lw;
            } else {
                float2 o0 = {v0, v1}, o1 = {v2, v3};
                *(float2*)&Cf[(size_t)r * N + c] = o0;
                *(float2*)&Cf[(size_t)(r + 8) * N + c] = o1;
            }
        }
    }
}

// ---------------------------------------------------------------------------
// FlashAttention, causal, split-bf16 3-term, ldmatrix + cp.async K/V pipeline.
// Q tile 128 rows, 8 warps. K/V tiles 64 keys, double-buffered.
// smem (words): Qh[0,4608) Ql[4608,9216); stage s at 9216+s*9216:
//   Kh[0,2304) Kl[2304,4608) Vh[4608,6912) Vl[6912,9216)   (all [64][36])
// V stays in NATURAL [key][dpair] layout; PV B-frags via ldmatrix.trans.
// ---------------------------------------------------------------------------
#define FL_SMEM ((9216 + 2 * 9216) * 4)

__global__ __launch_bounds__(256) void flash3(
    const u32* __restrict__ qh, const u32* __restrict__ ql,
    u32* __restrict__ ch, u32* __restrict__ cl)
{
    extern __shared__ u32 sm[];
    const u32 smbase = (u32)__cvta_generic_to_shared(sm);

    const int tid = threadIdx.x;
    const int lane = tid & 31, wid = tid >> 5;
    const int t = lane & 3, gsub = lane >> 2;
    const int bh = blockIdx.y, qt = blockIdx.x, q0 = qt * 128;
    const int b = bh >> 4, h = bh & 15;
    const size_t hw0 = (size_t)h * 96;

    const int lr = lane & 15;
    const u32 lc = (u32)((lane >> 4) * 16);
    // V trans lane geometry: key row + d-block select
    const int vkr = ((lane >> 3) & 1) * 8 + (lane & 7);
    const u32 vds = (u32)((lane >> 4) * 16);

#define ROWOFF(s_) ((size_t)(b * SS + (s_)) * NW3 + hw0)

#define FL_LOAD(s_, k0_) do {                                                 \
    u32* bse = sm + 9216 + (s_) * 9216;                                       \
    _Pragma("unroll")                                                         \
    for (int i_ = 0; i_ < 2; i_++) {                                          \
        int idx = tid + 256 * i_;                                             \
        int row = idx >> 3, q_ = idx & 7;                                     \
        size_t ro = ROWOFF((k0_) + row);                                      \
        int so = row * 36 + q_ * 4;                                           \
        cpasync16(bse + so,        qh + ro + 32 + q_ * 4);                    \
        cpasync16(bse + 2304 + so, ql + ro + 32 + q_ * 4);                    \
        cpasync16(bse + 4608 + so, qh + ro + 64 + q_ * 4);                    \
        cpasync16(bse + 6912 + so, ql + ro + 64 + q_ * 4);                    \
    } } while (0)

    // Kick off K/V stage 0 while we stage Q
    FL_LOAD(0, 0);
    cp_commit();

    // Load Q tile (hi/lo): 2048 uint4 units
#pragma unroll
    for (int i = 0; i < 8; i++) {
        int u = tid + 256 * i;
        int quad = u & 7, row = (u >> 3) & 127, hl = u >> 10;
        const u32* src = (hl ? ql : qh) + ROWOFF(q0 + row) + quad * 4;
        u32* dst = sm + hl * 4608 + row * 36 + quad * 4;
        *(uint4*)dst = *(const uint4*)src;
    }
    __syncthreads();

    // Hoist Q fragments via ldmatrix (rows wid*16 .. wid*16+15)
    u32 aqh[4][4], aql[4][4];
    {
        const u32 qb = smbase + (u32)((wid * 16 + lr) * 144) + lc;
#pragma unroll
        for (int ks = 0; ks < 4; ks++) {
            ldsm4(aqh[ks], qb + ks * 32);
            ldsm4(aql[ks], qb + 18432 + ks * 32);   // Ql offset 4608 words
        }
    }

    float m0 = -1e30f, m1 = -1e30f, l0 = 0.0f, l1 = 0.0f;
    float o[8][4];
#pragma unroll
    for (int j = 0; j < 8; j++)
#pragma unroll
        for (int e = 0; e < 4; e++) o[j][e] = 0.0f;

    const int nkt = 2 * qt + 2;
    for (int kt = 0; kt < nkt; kt++) {
        const int k0 = kt * 64;
        if (kt + 1 < nkt) {
            FL_LOAD((kt + 1) & 1, (kt + 1) * 64);
            cp_commit();
            cp_wait<1>();
        } else {
            cp_wait<0>();
        }
        __syncthreads();

        const u32 stb = smbase + (u32)((9216 + (kt & 1) * 9216) * 4);
        const u32 kbK  = stb + (u32)(lr * 144) + lc;           // Kh
        const u32 kbKl = kbK + 9216;                           // Kl (+2304 w)
        const u32 kbV  = stb + 18432 + (u32)(vkr * 144) + vds; // Vh (+4608 w)
        const u32 kbVl = kbV + 9216;                           // Vl

        // Scores S = Q @ K^T (3-term)
        float s[8][4];
#pragma unroll
        for (int j = 0; j < 8; j++)
#pragma unroll
            for (int e = 0; e < 4; e++) s[j][e] = 0.0f;

#pragma unroll
        for (int ks = 0; ks < 4; ks++) {
#pragma unroll
            for (int u = 0; u < 4; u++) {
                u32 kh[4], kl[4];
                ldsm4(kh, kbK  + u * 2304 + ks * 32);
                ldsm4(kl, kbKl + u * 2304 + ks * 32);
                mma_bf16(s[2 * u],     aqh[ks], kh[0], kh[2]);
                mma_bf16(s[2 * u],     aql[ks], kh[0], kh[2]);
                mma_bf16(s[2 * u],     aqh[ks], kl[0], kl[2]);
                mma_bf16(s[2 * u + 1], aqh[ks], kh[1], kh[3]);
                mma_bf16(s[2 * u + 1], aql[ks], kh[1], kh[3]);
                mma_bf16(s[2 * u + 1], aqh[ks], kl[1], kl[3]);
            }
        }

#pragma unroll
        for (int j = 0; j < 8; j++)
#pragma unroll
            for (int e = 0; e < 4; e++) s[j][e] *= 0.125f;

        if (kt >= 2 * qt) {   // diagonal region
            const int r0g = q0 + wid * 16 + gsub;
            const int r1g = r0g + 8;
#pragma unroll
            for (int j = 0; j < 8; j++) {
                int c0 = k0 + j * 8 + 2 * t;
                if (c0 > r0g)     s[j][0] = -1e30f;
                if (c0 + 1 > r0g) s[j][1] = -1e30f;
                if (c0 > r1g)     s[j][2] = -1e30f;
                if (c0 + 1 > r1g) s[j][3] = -1e30f;
            }
        }

        // Online softmax (quad-local reductions)
        float mt0 = -1e30f, mt1 = -1e30f;
#pragma unroll
        for (int j = 0; j < 8; j++) {
            mt0 = fmaxf(mt0, fmaxf(s[j][0], s[j][1]));
            mt1 = fmaxf(mt1, fmaxf(s[j][2], s[j][3]));
        }
        mt0 = fmaxf(mt0, __shfl_xor_sync(0xffffffffu, mt0, 1));
        mt0 = fmaxf(mt0, __shfl_xor_sync(0xffffffffu, mt0, 2));
        mt1 = fmaxf(mt1, __shfl_xor_sync(0xffffffffu, mt1, 1));
        mt1 = fmaxf(mt1, __shfl_xor_sync(0xffffffffu, mt1, 2));

        float mn0 = fmaxf(m0, mt0), mn1 = fmaxf(m1, mt1);
        float al0 = __expf(m0 - mn0), al1 = __expf(m1 - mn1);
        float rs0 = 0.0f, rs1 = 0.0f;
#pragma unroll
        for (int j = 0; j < 8; j++) {
            s[j][0] = __expf(s[j][0] - mn0);
            s[j][1] = __expf(s[j][1] - mn0);
            s[j][2] = __expf(s[j][2] - mn1);
            s[j][3] = __expf(s[j][3] - mn1);
            rs0 += s[j][0] + s[j][1];
            rs1 += s[j][2] + s[j][3];
        }
        rs0 += __shfl_xor_sync(0xffffffffu, rs0, 1);
        rs0 += __shfl_xor_sync(0xffffffffu, rs0, 2);
        rs1 += __shfl_xor_sync(0xffffffffu, rs1, 1);
        rs1 += __shfl_xor_sync(0xffffffffu, rs1, 2);

        l0 = l0 * al0 + rs0;  l1 = l1 * al1 + rs1;
        m0 = mn0;             m1 = mn1;
#pragma unroll
        for (int j = 0; j < 8; j++) {
            o[j][0] *= al0; o[j][1] *= al0;
            o[j][2] *= al1; o[j][3] *= al1;
        }

        // O += P @ V (P in registers; V natural layout via ldmatrix.trans)
#pragma unroll
        for (int kk = 0; kk < 4; kk++) {
            u32 ph[4], pl[4];
            split2(s[2 * kk][0],     s[2 * kk][1],     ph[0], pl[0]);
            split2(s[2 * kk][2],     s[2 * kk][3],     ph[1], pl[1]);
            split2(s[2 * kk + 1][0], s[2 * kk + 1][1], ph[2], pl[2]);
            split2(s[2 * kk + 1][2], s[2 * kk + 1][3], ph[3], pl[3]);
#pragma unroll
            for (int u = 0; u < 4; u++) {
                u32 vh[4], vl[4];
                ldsm4t(vh, kbV  + kk * 2304 + u * 32);
                ldsm4t(vl, kbVl + kk * 2304 + u * 32);
                // regs: r0=b0(j=2u) r1=b1(j=2u) r2=b0(j=2u+1) r3=b1(j=2u+1)
                mma_bf16(o[2 * u],     ph, vh[0], vh[1]);
                mma_bf16(o[2 * u],     pl, vh[0], vh[1]);
                mma_bf16(o[2 * u],     ph, vl[0], vl[1]);
                mma_bf16(o[2 * u + 1], ph, vh[2], vh[3]);
                mma_bf16(o[2 * u + 1], pl, vh[2], vh[3]);
                mma_bf16(o[2 * u + 1], ph, vl[2], vl[3]);
            }
        }
        __syncthreads();
    }

    // Epilogue: normalize, split, store to ctx [B,H,S,D]-flat (32 words/row)
    const float i0 = 1.0f / l0, i1 = 1.0f / l1;
    const size_t orow = ((size_t)bh * SS + q0 + wid * 16 + gsub) * 32;
#pragma unroll
    for (int j = 0; j < 8; j++) {
        int wc = 4 * j + t;
        u32 hw, lw;
        split2(o[j][0] * i0, o[j][1] * i0, hw, lw);
        ch[orow + wc] = hw;  cl[orow + wc] = lw;
        split2(o[j][2] * i1, o[j][3] * i1, hw, lw);
        ch[orow + 256 + wc] = hw;  cl[orow + 256 + wc] = lw;  // +8 rows
    }
#undef FL_LOAD
#undef ROWOFF
}

// ---------------------------------------------------------------------------
// Launch
// ---------------------------------------------------------------------------
extern "C" void kernel_launch(void* const* d_in, const int* in_sizes, int n_in,
                              void* d_out, int out_size)
{
    const float* x    = (const float*)d_in[0];
    // d_in[1] = causal mask (tril -> handled analytically)
    const float* Wqkv = (const float*)d_in[2];
    const float* bqkv = (const float*)d_in[3];
    const float* Wo   = (const float*)d_in[4];
    const float* bo   = (const float*)d_in[5];
    float* out = (float*)d_out;

    u32 *xh, *xl, *wqh, *wql, *woh, *wol, *qkvh, *qkvl, *ctxh, *ctxl;
    cudaGetSymbolAddress((void**)&xh, g_xh);
    cudaGetSymbolAddress((void**)&xl, g_xl);
    cudaGetSymbolAddress((void**)&wqh, g_wqh);
    cudaGetSymbolAddress((void**)&wql, g_wql);
    cudaGetSymbolAddress((void**)&woh, g_woh);
    cudaGetSymbolAddress((void**)&wol, g_wol);
    cudaGetSymbolAddress((void**)&qkvh, g_qkvh);
    cudaGetSymbolAddress((void**)&qkvl, g_qkvl);
    cudaGetSymbolAddress((void**)&ctxh, g_ctxh);
    cudaGetSymbolAddress((void**)&ctxl, g_ctxl);

    cudaFuncSetAttribute(gemm3<1>, cudaFuncAttributeMaxDynamicSharedMemorySize,
                         GEMM_SMEM);
    cudaFuncSetAttribute(gemm3<0>, cudaFuncAttributeMaxDynamicSharedMemorySize,
                         GEMM_SMEM);
    cudaFuncSetAttribute(flash3, cudaFuncAttributeMaxDynamicSharedMemorySize,
                         FL_SMEM);

    // 0) split inputs (x pairwise; weights transposed into k-pair layout)
    {
        int nx = NROWS * EW;
        int nq = K3E * EW;
        int no = EE * EW;
        split_kernel<<<(nx + 255) / 256, 256>>>(x, xh, xl, nx);
        splitT_kernel<<<(nq + 255) / 256, 256>>>(Wqkv, wqh, wql, K3E, EE);
        splitT_kernel<<<(no + 255) / 256, 256>>>(Wo, woh, wol, EE, EE);
    }
    // 1) QKV projection -> split qkv
    {
        dim3 grid(K3E / 128, NROWS / 128);   // (24, 64)
        gemm3<1><<<grid, 256, GEMM_SMEM>>>(xh, xl, wqh, wql, bqkv,
                                           nullptr, qkvh, qkvl,
                                           NROWS, K3E, EE);
    }
    // 2) Causal flash attention -> split ctx
    {
        dim3 grid(SS / 128, BB * HH);        // (16, 64)
        flash3<<<grid, 256, FL_SMEM>>>(qkvh, qkvl, ctxh, ctxl);
    }
    // 3) Output projection -> fp32 out
    {
        dim3 grid(EE / 128, NROWS / 128);    // (8, 64)
        gemm3<0><<<grid, 256, GEMM_SMEM>>>(ctxh, ctxl, woh, wol, bo,
                                           out, nullptr, nullptr,
                                           NROWS, EE, EE);
    }
}